// round 2
// baseline (speedup 1.0000x reference)
#include <cuda_runtime.h>
#include <cstdint>

#define BB 8192
#define TT 2048
#define NN 60
#define THREADS 256          // 8 warps per block
#define BLOCKS 1024          // 8192 warps total -> one row per warp
#define WARPS_TOTAL (BLOCKS * (THREADS / 32))

// Key math: mul is a group Cayley table, so the T-step scan
//   s_t = mul[x_t, s_{t-1}], s_0 = identity (0)
// collapses to the ordered product s = x_T * ... * x_1 (associativity).
// The dataset's table is the cyclic group mul[a,b] = (a+b) % N; each block
// verifies this while loading the table, and when it holds the product is
// simply (sum of x_t) % N — a pure HBM-bound sum reduction.
// A generic ordered-product fallback (warp butterfly over the smem table)
// keeps correctness for any group table.
__global__ __launch_bounds__(THREADS, 8)
void a5_scan_kernel(const float* __restrict__ scale_p,
                    const int*   __restrict__ ids,
                    const int*   __restrict__ mul,
                    float*       __restrict__ out) {
    __shared__ int s_mul[NN * NN];   // 14400 B

    const int tid  = threadIdx.x;
    const int lane = tid & 31;
    const int wid  = tid >> 5;
    const int gwarp = blockIdx.x * (THREADS / 32) + wid;

    // Cooperative table load + structure verification
    bool ok = true;
    for (int i = tid; i < NN * NN; i += THREADS) {
        int v = mul[i];
        s_mul[i] = v;
        int a = i / NN;
        int b = i - a * NN;
        ok &= (v == (a + b) % NN);
    }
    const bool cyclic = (__syncthreads_and(ok ? 1 : 0) != 0);

    const float scale = *scale_p;
    const float hi = 10.0f * scale;
    const float lo = -10.0f * scale;

    for (int row = gwarp; row < BB; row += WARPS_TOTAL) {
        const int4* rp = reinterpret_cast<const int4*>(ids + (size_t)row * TT);
        // Chunk c (c = i*32 + lane) covers times [4c, 4c+4): 16 coalesced
        // 128-bit loads per lane, time order == chunk index order.
        int4 v[16];
        #pragma unroll
        for (int i = 0; i < 16; i++)
            v[i] = rp[i * 32 + lane];

        int s;
        if (cyclic) {
            int sum = 0;
            #pragma unroll
            for (int i = 0; i < 16; i++)
                sum += v[i].x + v[i].y + v[i].z + v[i].w;
            sum = __reduce_add_sync(0xffffffffu, sum);   // REDUX, no smem
            s = sum % NN;
        } else {
            // Ordered product per chunk of 4 consecutive times t0<t1<t2<t3:
            // p = x3*x2*x1*x0 with a*b = mul[a][b].
            int p[16];
            #pragma unroll
            for (int i = 0; i < 16; i++) {
                int a = s_mul[v[i].y * NN + v[i].x];
                int b = s_mul[v[i].w * NN + v[i].z];
                p[i] = s_mul[b * NN + a];
            }
            // For each i, butterfly-combine the 32 chunks (lane order = time
            // order): after step with offset o, every lane holds the ordered
            // product of its 2o-sized group (later half * earlier half).
            #pragma unroll
            for (int i = 0; i < 16; i++) {
                int x = p[i];
                #pragma unroll
                for (int o = 1; o < 32; o <<= 1) {
                    int other = __shfl_xor_sync(0xffffffffu, x, o);
                    x = (lane & o) ? s_mul[x * NN + other]
                                   : s_mul[other * NN + x];
                }
                p[i] = x;
            }
            // Combine the 16 group products in time order (later * earlier).
            int acc = p[0];
            #pragma unroll
            for (int i = 1; i < 16; i++)
                acc = s_mul[p[i] * NN + acc];
            s = acc;
        }

        // 60 outputs per row: lanes 0-31 write col lane, lanes 0-27 also
        // write col lane+32. Coalesced 240-byte stores.
        float* op = out + (size_t)row * NN;
        op[lane] = (lane == s) ? hi : lo;
        if (lane < NN - 32)
            op[lane + 32] = (lane + 32 == s) ? hi : lo;
    }
}

extern "C" void kernel_launch(void* const* d_in, const int* in_sizes, int n_in,
                              void* d_out, int out_size) {
    // Identify inputs by element count (robust to ordering):
    //   scale: 1 element, mul: 3600 elements, input_ids: B*T (largest)
    const float* scale = nullptr;
    const int*   ids   = nullptr;
    const int*   mul   = nullptr;
    for (int i = 0; i < n_in; i++) {
        if (in_sizes[i] == 1)               scale = (const float*)d_in[i];
        else if (in_sizes[i] == NN * NN)    mul   = (const int*)d_in[i];
        else                                ids   = (const int*)d_in[i];
    }
    a5_scan_kernel<<<BLOCKS, THREADS>>>(scale, ids, mul, (float*)d_out);
}

// round 3
// speedup vs baseline: 3.2593x; 3.2593x over previous
#include <cuda_runtime.h>
#include <cstdint>

#define BB 8192
#define TT 2048
#define NN 60
#define THREADS 64               // 2 warps per block
#define WARPS_PER_BLOCK (THREADS / 32)
#define BLOCKS (BB / WARPS_PER_BLOCK)   // 4096 blocks, one row per warp

// Math: mul is a group Cayley table, so the T-step scan
//   s_t = mul[x_t, s_{t-1}], s_0 = identity (0)
// collapses to the ordered product s = x_T * ... * x_1 (associativity only).
// The dataset's table is cyclic Z_60 (mul[a,b] = (a+b) % N): then the ordered
// product is (sum of x_t) % N — a pure HBM-bound sum reduction.
// A 1-block pre-kernel verifies the structure once and publishes a flag;
// the main kernel is table-free and smem-free on the fast path. A generic
// ordered-product fallback (warp butterfly over the L2-hot global table)
// preserves correctness for any group table.

__device__ int g_cyclic;

__global__ void check_cyclic_kernel(const int* __restrict__ mul) {
    int ok = 1;
    for (int i = threadIdx.x; i < NN * NN; i += blockDim.x) {
        int a = i / NN;
        int b = i - a * NN;
        ok &= (mul[i] == (a + b) % NN);
    }
    ok = __syncthreads_and(ok);
    if (threadIdx.x == 0) g_cyclic = ok;
}

__global__ __launch_bounds__(THREADS)
void a5_scan_kernel(const float* __restrict__ scale_p,
                    const int*   __restrict__ ids,
                    const int*   __restrict__ mul,
                    float*       __restrict__ out) {
    const int lane = threadIdx.x & 31;
    const int row  = blockIdx.x * WARPS_PER_BLOCK + (threadIdx.x >> 5);
    if (row >= BB) return;

    const int cyclic = g_cyclic;
    const float scale = __ldg(scale_p);
    const float hi = 10.0f * scale;
    const float lo = -10.0f * scale;

    const int4* rp = reinterpret_cast<const int4*>(ids + (size_t)row * TT);
    // Chunk c = i*32 + lane covers times [4c, 4c+4): 16 coalesced streaming
    // 128-bit loads per lane; chunk-index order == time order.
    int4 v[16];
    #pragma unroll
    for (int i = 0; i < 16; i++)
        v[i] = __ldcs(&rp[i * 32 + lane]);

    int s;
    if (cyclic) {
        int sum = 0;
        #pragma unroll
        for (int i = 0; i < 16; i++)
            sum += v[i].x + v[i].y + v[i].z + v[i].w;
        sum = __reduce_add_sync(0xffffffffu, sum);   // REDUX, no smem
        s = sum % NN;
    } else {
        // Generic ordered product (correctness path only; table is 14 KB,
        // L2-hot across all blocks). Per chunk of 4 times t0<t1<t2<t3:
        // p = x3*x2*x1*x0 with a*b = mul[a][b].
        int p[16];
        #pragma unroll
        for (int i = 0; i < 16; i++) {
            int a = __ldg(&mul[v[i].y * NN + v[i].x]);
            int b = __ldg(&mul[v[i].w * NN + v[i].z]);
            p[i] = __ldg(&mul[b * NN + a]);
        }
        // Butterfly-combine the 32 chunks of each i (lane order = time
        // order): after offset o, each lane holds the ordered product of
        // its 2o-sized group (later half * earlier half).
        #pragma unroll
        for (int i = 0; i < 16; i++) {
            int x = p[i];
            #pragma unroll
            for (int o = 1; o < 32; o <<= 1) {
                int other = __shfl_xor_sync(0xffffffffu, x, o);
                x = (lane & o) ? __ldg(&mul[x * NN + other])
                               : __ldg(&mul[other * NN + x]);
            }
            p[i] = x;
        }
        int acc = p[0];
        #pragma unroll
        for (int i = 1; i < 16; i++)
            acc = __ldg(&mul[p[i] * NN + acc]);
        s = acc;
    }

    // 60 outputs per row: lanes 0-31 write col lane; lanes 0-27 also write
    // col lane+32. Coalesced 240-byte row stores.
    float* op = out + (size_t)row * NN;
    op[lane] = (lane == s) ? hi : lo;
    if (lane < NN - 32)
        op[lane + 32] = (lane + 32 == s) ? hi : lo;
}

extern "C" void kernel_launch(void* const* d_in, const int* in_sizes, int n_in,
                              void* d_out, int out_size) {
    // Identify inputs by element count (robust to ordering):
    //   scale: 1 element, mul: 3600 elements, input_ids: B*T (largest)
    const float* scale = nullptr;
    const int*   ids   = nullptr;
    const int*   mul   = nullptr;
    for (int i = 0; i < n_in; i++) {
        if (in_sizes[i] == 1)               scale = (const float*)d_in[i];
        else if (in_sizes[i] == NN * NN)    mul   = (const int*)d_in[i];
        else                                ids   = (const int*)d_in[i];
    }
    check_cyclic_kernel<<<1, 1024>>>(mul);
    a5_scan_kernel<<<BLOCKS, THREADS>>>(scale, ids, mul, (float*)d_out);
}